// round 9
// baseline (speedup 1.0000x reference)
#include <cuda_runtime.h>
#include <cuda_fp16.h>
#include <math.h>

// Problem dims (fixed by the dataset)
#define NN 4
#define HH 512
#define WW 512
#define CC 64

#define CPB     64                 // channels per block = full row
#define THREADS 512
#define ROWLEN  512
#define NCHUNK  16                 // one warp per chunk
#define CLEN    (ROWLEN / NCHUNK)  // 32  (cross-chunk leak 0.5^32 ~ 2e-10)
#define H2PW    (CPB / 2)          // half2 per scan-site = 32
#define VECH    (ROWLEN * CPB / 8) // uint4 (8 halves) per fp16 tile = 4096
#define SMEM_BYTES (ROWLEN * CPB * 2) // 65536 dynamic (fp16 tile -> 3 CTAs/SM)

// Intermediate (W-filtered) image in fp16, same NHWC index space as x.
__device__ __half g_scratch[(size_t)NN * HH * WW * CC];

// Chunk-local scan + analytic correction, per (chunk=warp, c2=lane):
//  B) forward local scan u_w (zero carry-in; chunk 0 uses exact init x[0]);
//     publish E_k = u end value.                       [serial 32, 1 barrier]
//  C) backward local scan over corrected y_w = u_w + 0.5^{w-w0+1} E_{k-1}
//     (correction fma off the carry chain); chunk 15 inits exactly with
//     z = y[L-1]; publish F_k = z at w0.               [serial 32, 1 barrier]
//  D) final parallel sweep  z_w = zloc_w + 0.5^{w1-w} F_{k+1}, fused with
//     the gmem epilogue (independent iterations -> full MLP).
// Phases B/C/D below are inlined in each pass kernel.

// ---- Pass 1: IIR along W; one block per (n*H) row, all 64 channels ----
__global__ void __launch_bounds__(THREADS, 3)
pass1_kernel(const float* __restrict__ x) {
    extern __shared__ __half2 s2[];
    __shared__ float2 Earr[NCHUNK][H2PW];
    __shared__ float2 Farr[NCHUNK][H2PW];
    uint4* s4 = reinterpret_cast<uint4*>(s2);

    const int    nh   = blockIdx.x;                 // n*HH + h
    const size_t base = (size_t)nh * (WW * CC);

    // Load + fp32->fp16: per w, 64 ch = 8 uint4 of 8 halves.
    #pragma unroll
    for (int i = threadIdx.x; i < VECH; i += THREADS) {
        const int w = i >> 3;
        const int q = i & 7;
        const float4 a = __ldcs((const float4*)(x + base + (size_t)w * CC + q * 8));
        const float4 b = __ldcs((const float4*)(x + base + (size_t)w * CC + q * 8 + 4));
        __half2 hv[4];
        hv[0] = __floats2half2_rn(a.x, a.y);
        hv[1] = __floats2half2_rn(a.z, a.w);
        hv[2] = __floats2half2_rn(b.x, b.y);
        hv[3] = __floats2half2_rn(b.z, b.w);
        s4[w * 8 + q] = *(uint4*)hv;
    }
    __syncthreads();

    const int c2    = threadIdx.x & 31;
    const int chunk = threadIdx.x >> 5;
    const int w0    = chunk * CLEN;
    const int w1    = w0 + CLEN;

    // ---- B: forward local scan ----
    float2 carry = make_float2(0.f, 0.f);
    if (chunk == 0) carry = __half22float2(s2[c2]);      // exact init: x[0]
    #pragma unroll
    for (int w = w0; w < w1; ++w) {
        const float2 v = __half22float2(s2[w * H2PW + c2]);
        carry.x = fmaf(0.5f, carry.x, 0.5f * v.x);
        carry.y = fmaf(0.5f, carry.y, 0.5f * v.y);
        s2[w * H2PW + c2] = __floats2half2_rn(carry.x, carry.y);
    }
    Earr[chunk][c2] = carry;
    __syncthreads();

    // ---- C: backward local scan over corrected forward values ----
    const float2 Ep = (chunk > 0) ? Earr[chunk - 1][c2] : make_float2(0.f, 0.f);
    float2 carry2 = make_float2(0.f, 0.f);
    if (chunk == NCHUNK - 1) {                           // exact init: y[L-1]
        float2 yl = __half22float2(s2[(ROWLEN - 1) * H2PW + c2]);
        carry2.x = fmaf(0x1p-32f, Ep.x, yl.x);
        carry2.y = fmaf(0x1p-32f, Ep.y, yl.y);
    }
    float df = 0x1p-32f;                                 // 0.5^{w-w0+1} at w1-1
    #pragma unroll
    for (int w = w1 - 1; w >= w0; --w) {
        float2 y = __half22float2(s2[w * H2PW + c2]);
        y.x = fmaf(df, Ep.x, y.x);                       // off carry chain
        y.y = fmaf(df, Ep.y, y.y);
        carry2.x = fmaf(0.5f, carry2.x, 0.5f * y.x);
        carry2.y = fmaf(0.5f, carry2.y, 0.5f * y.y);
        s2[w * H2PW + c2] = __floats2half2_rn(carry2.x, carry2.y);
        df *= 2.f;
    }
    Farr[chunk][c2] = carry2;
    __syncthreads();

    // ---- D: parallel correction sweep, streamed to scratch ----
    const float2 Fn = (chunk < NCHUNK - 1) ? Farr[chunk + 1][c2]
                                           : make_float2(0.f, 0.f);
    float ef = 0x1p-32f;                                 // 0.5^{w1-w} at w0
    #pragma unroll
    for (int w = w0; w < w1; ++w) {
        float2 z = __half22float2(s2[w * H2PW + c2]);
        z.x = fmaf(ef, Fn.x, z.x);
        z.y = fmaf(ef, Fn.y, z.y);
        const __half2 hz = __floats2half2_rn(z.x, z.y);
        __stcs((unsigned int*)(g_scratch + base + (size_t)w * CC) + c2,
               *(const unsigned int*)&hz);
        ef *= 2.f;
    }
}

// ---- Pass 2: IIR along H on the scratch + residual mix -> out ----
__global__ void __launch_bounds__(THREADS, 3)
pass2_kernel(const float* __restrict__ x,
             const float* __restrict__ alpha,
             float*       __restrict__ out) {
    extern __shared__ __half2 s2[];
    __shared__ float2 Earr[NCHUNK][H2PW];
    __shared__ float2 Farr[NCHUNK][H2PW];
    __shared__ __align__(16) float sm[CPB];
    uint4* s4 = reinterpret_cast<uint4*>(s2);

    const int    nw   = blockIdx.x;                 // n*WW + w
    const int    n    = nw >> 9;
    const int    w    = nw & 511;
    const size_t base = (size_t)n * (HH * WW * CC) + (size_t)w * CC;

    if (threadIdx.x < CPB)
        sm[threadIdx.x] = 1.0f / (1.0f + expf(-alpha[threadIdx.x]));

    // Raw fp16 copy scratch -> smem: per h, 8 uint4 (128B row-step).
    #pragma unroll
    for (int i = threadIdx.x; i < VECH; i += THREADS) {
        const int h = i >> 3;
        const int q = i & 7;
        s4[h * 8 + q] =
            *(const uint4*)(g_scratch + base + (size_t)h * (WW * CC) + q * 8);
    }
    __syncthreads();

    const int c2    = threadIdx.x & 31;
    const int chunk = threadIdx.x >> 5;
    const int h0    = chunk * CLEN;
    const int h1    = h0 + CLEN;

    // ---- B: forward local scan ----
    float2 carry = make_float2(0.f, 0.f);
    if (chunk == 0) carry = __half22float2(s2[c2]);      // exact init: z[0]
    #pragma unroll
    for (int h = h0; h < h1; ++h) {
        const float2 v = __half22float2(s2[h * H2PW + c2]);
        carry.x = fmaf(0.5f, carry.x, 0.5f * v.x);
        carry.y = fmaf(0.5f, carry.y, 0.5f * v.y);
        s2[h * H2PW + c2] = __floats2half2_rn(carry.x, carry.y);
    }
    Earr[chunk][c2] = carry;
    __syncthreads();

    // ---- C: backward local scan over corrected forward values ----
    const float2 Ep = (chunk > 0) ? Earr[chunk - 1][c2] : make_float2(0.f, 0.f);
    float2 carry2 = make_float2(0.f, 0.f);
    if (chunk == NCHUNK - 1) {
        float2 yl = __half22float2(s2[(ROWLEN - 1) * H2PW + c2]);
        carry2.x = fmaf(0x1p-32f, Ep.x, yl.x);
        carry2.y = fmaf(0x1p-32f, Ep.y, yl.y);
    }
    float df = 0x1p-32f;
    #pragma unroll
    for (int h = h1 - 1; h >= h0; --h) {
        float2 y = __half22float2(s2[h * H2PW + c2]);
        y.x = fmaf(df, Ep.x, y.x);
        y.y = fmaf(df, Ep.y, y.y);
        carry2.x = fmaf(0.5f, carry2.x, 0.5f * y.x);
        carry2.y = fmaf(0.5f, carry2.y, 0.5f * y.y);
        s2[h * H2PW + c2] = __floats2half2_rn(carry2.x, carry2.y);
        df *= 2.f;
    }
    Farr[chunk][c2] = carry2;
    __syncthreads();

    // ---- D: parallel correction + residual epilogue (full MLP) ----
    const float2 Fn = (chunk < NCHUNK - 1) ? Farr[chunk + 1][c2]
                                           : make_float2(0.f, 0.f);
    const float2 mv = *(const float2*)(&sm[c2 * 2]);
    float ef = 0x1p-32f;
    #pragma unroll
    for (int h = h0; h < h1; ++h) {
        float2 z = __half22float2(s2[h * H2PW + c2]);
        z.x = fmaf(ef, Fn.x, z.x);
        z.y = fmaf(ef, Fn.y, z.y);
        const size_t g  = base + (size_t)h * (WW * CC) + c2 * 2;
        const float2 xv = __ldcs((const float2*)(x + g));
        float2 o;
        o.x = fmaf(mv.x, z.x - xv.x, xv.x);
        o.y = fmaf(mv.y, z.y - xv.y, xv.y);
        __stcs((float2*)(out + g), o);
        ef *= 2.f;
    }
}

extern "C" void kernel_launch(void* const* d_in, const int* in_sizes, int n_in,
                              void* d_out, int out_size) {
    const float* x     = (const float*)d_in[0];
    const float* alpha = (const float*)d_in[1];
    float*       out   = (float*)d_out;

    // >48KB dynamic smem opt-in (idempotent, capture-safe).
    cudaFuncSetAttribute(pass1_kernel,
                         cudaFuncAttributeMaxDynamicSharedMemorySize, SMEM_BYTES);
    cudaFuncSetAttribute(pass2_kernel,
                         cudaFuncAttributeMaxDynamicSharedMemorySize, SMEM_BYTES);

    pass1_kernel<<<NN * HH, THREADS, SMEM_BYTES>>>(x);
    pass2_kernel<<<NN * WW, THREADS, SMEM_BYTES>>>(x, alpha, out);
}

// round 10
// speedup vs baseline: 1.0352x; 1.0352x over previous
#include <cuda_runtime.h>
#include <cuda_fp16.h>
#include <math.h>

// Problem dims (fixed by the dataset)
#define NN 4
#define HH 512
#define WW 512
#define CC 64

#define CPB     64                 // channels per tile = full row
#define THREADS 512
#define ROWLEN  512
#define NCHUNK  16                 // one warp per chunk; lane = half2 channel pair
#define CLEN    (ROWLEN / NCHUNK)  // 32
#define LWARM   16                 // warm-up: err ~ 0.5^17 ~ 8e-6
#define H2PW    (CPB / 2)          // half2 per scan-site = 32
#define VECH    (ROWLEN * CPB / 8) // uint4 (8 halves) per fp16 tile = 4096
#define VEC     (ROWLEN * CPB / 4) // float4 items (epilogue) = 8192
#define SMEM_BYTES (ROWLEN * CPB * 2) // 65536 (fp16 tile -> 3 CTAs/SM)

#define NTILES_P1 (NN * HH)        // 2048
#define NTILES_P2 (NN * WW)        // 2048
#define NTILES    (NTILES_P1 + NTILES_P2)
#define GRID      456              // 152 SMs x 3 resident CTAs

// Intermediate (W-filtered) image in fp16, same NHWC index space as x.
__device__ __half g_scratch[(size_t)NN * HH * WW * CC];
__device__ int    g_queue;         // next queue slot
__device__ int    g_done[NN];      // pass1 rows completed per image

__global__ void init_kernel() {
    if (threadIdx.x == 0) g_queue = 0;
    if (threadIdx.x < NN) g_done[threadIdx.x] = 0;
}

// ---- R7 tile bodies, verbatim structure ----

// Fwd+bwd IIR (a=b=0.5) over a ROWLEN x CC half2 tile in smem, in place.
// fp32 carry chains in registers; boundary chunks exact w.r.t. reference
// inits (carry = s[0] fwd; carry = s[L-1] = y_f[L-1] bwd).
__device__ __forceinline__ void iir_scan_tile_h2(__half2* s, int tid) {
    const int c     = tid & 31;
    const int chunk = tid >> 5;
    const int w0    = chunk * CLEN;
    const int w1    = w0 + CLEN;

    int ws = w0 - LWARM; if (ws < 0) ws = 0;
    float2 carry = __half22float2(s[ws * H2PW + c]);
    for (int w = ws; w < w0; ++w) {
        const float2 v = __half22float2(s[w * H2PW + c]);
        carry.x = fmaf(0.5f, carry.x, 0.5f * v.x);
        carry.y = fmaf(0.5f, carry.y, 0.5f * v.y);
    }
    __syncthreads();

    #pragma unroll
    for (int w = w0; w < w1; ++w) {
        const float2 v = __half22float2(s[w * H2PW + c]);
        carry.x = fmaf(0.5f, carry.x, 0.5f * v.x);
        carry.y = fmaf(0.5f, carry.y, 0.5f * v.y);
        s[w * H2PW + c] = __floats2half2_rn(carry.x, carry.y);
    }
    __syncthreads();

    int we = w1 - 1 + LWARM; if (we > ROWLEN - 1) we = ROWLEN - 1;
    carry = __half22float2(s[we * H2PW + c]);
    for (int w = we - 1; w >= w1; --w) {
        const float2 v = __half22float2(s[w * H2PW + c]);
        carry.x = fmaf(0.5f, carry.x, 0.5f * v.x);
        carry.y = fmaf(0.5f, carry.y, 0.5f * v.y);
    }
    __syncthreads();

    #pragma unroll
    for (int w = w1 - 1; w >= w0; --w) {
        const float2 v = __half22float2(s[w * H2PW + c]);
        carry.x = fmaf(0.5f, carry.x, 0.5f * v.x);
        carry.y = fmaf(0.5f, carry.y, 0.5f * v.y);
        s[w * H2PW + c] = __floats2half2_rn(carry.x, carry.y);
    }
    __syncthreads();
}

// W-direction IIR over row `nh` (= n*HH + h): x fp32 -> scan -> scratch fp16.
__device__ __forceinline__ void do_pass1(const float* __restrict__ x,
                                         int nh, __half2* s2) {
    uint4* s4 = reinterpret_cast<uint4*>(s2);
    const size_t base = (size_t)nh * (WW * CC);

    #pragma unroll
    for (int i = threadIdx.x; i < VECH; i += THREADS) {
        const int w = i >> 3;
        const int q = i & 7;
        const float4 a = *(const float4*)(x + base + (size_t)w * CC + q * 8);
        const float4 b = *(const float4*)(x + base + (size_t)w * CC + q * 8 + 4);
        __half2 hv[4];
        hv[0] = __floats2half2_rn(a.x, a.y);
        hv[1] = __floats2half2_rn(a.z, a.w);
        hv[2] = __floats2half2_rn(b.x, b.y);
        hv[3] = __floats2half2_rn(b.z, b.w);
        s4[w * 8 + q] = *(uint4*)hv;
    }
    __syncthreads();

    iir_scan_tile_h2(s2, threadIdx.x);

    #pragma unroll
    for (int i = threadIdx.x; i < VECH; i += THREADS) {
        const int w = i >> 3;
        const int q = i & 7;
        *(uint4*)(g_scratch + base + (size_t)w * CC + q * 8) = s4[w * 8 + q];
    }
}

// H-direction IIR over column `nw` (= n*WW + w) + residual mix -> out.
__device__ __forceinline__ void do_pass2(const float* __restrict__ x,
                                         const float* sm,   // sigmoid(alpha)
                                         float* __restrict__ out,
                                         int nw, __half2* s2) {
    uint4* s4 = reinterpret_cast<uint4*>(s2);
    const int    n    = nw >> 9;
    const int    w    = nw & 511;
    const size_t base = (size_t)n * (HH * WW * CC) + (size_t)w * CC;

    #pragma unroll
    for (int i = threadIdx.x; i < VECH; i += THREADS) {
        const int h = i >> 3;
        const int q = i & 7;
        s4[h * 8 + q] = *(const uint4*)(g_scratch + base + (size_t)h * (WW * CC) + q * 8);
    }
    __syncthreads();

    iir_scan_tile_h2(s2, threadIdx.x);

    #pragma unroll
    for (int i = threadIdx.x; i < VEC; i += THREADS) {
        const int    h  = i >> 4;                   // 16 float4 per h
        const int    c4 = i & 15;
        const size_t g  = base + (size_t)h * (WW * CC) + c4 * 4;
        const float4 xv = *(const float4*)(x + g);
        const __half2* hp = (const __half2*)(s2 + h * H2PW + c4 * 2);
        const float2 y0 = __half22float2(hp[0]);
        const float2 y1 = __half22float2(hp[1]);
        const float4 mv = *(const float4*)(&sm[c4 * 4]);
        float4 o;
        o.x = fmaf(mv.x, y0.x - xv.x, xv.x);
        o.y = fmaf(mv.y, y0.y - xv.y, xv.y);
        o.z = fmaf(mv.z, y1.x - xv.z, xv.z);
        o.w = fmaf(mv.w, y1.y - xv.w, xv.w);
        *(float4*)(out + g) = o;
    }
}

// Queue order: [p1 image0 (512)] ++ interleave{p1 images1-3, p2 images0-2}
// (3072, alternating) ++ [p2 image3 (512)]. p1 tiles precede their p2
// consumers, so spins always terminate (p1 tiles never wait -> no deadlock).
__device__ __forceinline__ void map_queue(int q, int& role, int& tile) {
    if (q < 512)            { role = 0; tile = q; }
    else if (q < 512 + 3072) {
        const int j = q - 512;
        if ((j & 1) == 0)   { role = 0; tile = 512 + (j >> 1); }
        else                { role = 1; tile = j >> 1; }
    }
    else                    { role = 1; tile = 1536 + (q - (512 + 3072)); }
}

__global__ void __launch_bounds__(THREADS, 3)
iir_persistent_kernel(const float* __restrict__ x,
                      const float* __restrict__ alpha,
                      float*       __restrict__ out) {
    extern __shared__ __half2 s2[];
    __shared__ __align__(16) float sm[CPB];
    __shared__ int s_q;

    if (threadIdx.x < CPB)
        sm[threadIdx.x] = 1.0f / (1.0f + expf(-alpha[threadIdx.x]));
    // sm is read only in p2 epilogues, always separated from here by syncs.

    while (true) {
        if (threadIdx.x == 0) s_q = atomicAdd(&g_queue, 1);
        __syncthreads();                    // claim visible + smem reuse fence
        const int q = s_q;
        if (q >= NTILES) break;

        int role, tile;
        map_queue(q, role, tile);

        if (role == 0) {
            do_pass1(x, tile, s2);
            __threadfence();                // publish scratch stores (all threads)
            __syncthreads();
            if (threadIdx.x == 0)
                atomicAdd(&g_done[tile >> 9], 1);
        } else {
            if (threadIdx.x == 0) {
                const int n = tile >> 9;
                while (atomicAdd(&g_done[n], 0) < HH) __nanosleep(128);
                __threadfence();            // acquire scratch visibility
            }
            __syncthreads();
            do_pass2(x, sm, out, tile, s2);
        }
    }
}

extern "C" void kernel_launch(void* const* d_in, const int* in_sizes, int n_in,
                              void* d_out, int out_size) {
    const float* x     = (const float*)d_in[0];
    const float* alpha = (const float*)d_in[1];
    float*       out   = (float*)d_out;

    // >48KB dynamic smem opt-in (idempotent, capture-safe).
    cudaFuncSetAttribute(iir_persistent_kernel,
                         cudaFuncAttributeMaxDynamicSharedMemorySize, SMEM_BYTES);

    init_kernel<<<1, 32>>>();
    iir_persistent_kernel<<<GRID, THREADS, SMEM_BYTES>>>(x, alpha, out);
}

// round 11
// speedup vs baseline: 1.1078x; 1.0701x over previous
#include <cuda_runtime.h>
#include <cuda_fp16.h>
#include <math.h>

// Problem dims (fixed by the dataset)
#define NN 4
#define HH 512
#define WW 512
#define CC 64

#define CPB     64                 // channels per tile = full row
#define THREADS 512
#define ROWLEN  512
#define NCHUNK  16                 // one warp per chunk; lane = half2 channel pair
#define CLEN    (ROWLEN / NCHUNK)  // 32
#define LWARM   16                 // warm-up: err ~ 0.5^17 ~ 8e-6
#define H2PW    (CPB / 2)          // half2 per scan-site = 32
#define VECH    (ROWLEN * CPB / 8) // uint4 (8 halves) per fp16 tile = 4096
#define VEC     (ROWLEN * CPB / 4) // float4 items (epilogue) = 8192
#define SMEM_BYTES (ROWLEN * CPB * 2) // 65536 (fp16 tile -> 3 CTAs/SM)

#define NTILES_P1 (NN * HH)        // 2048
#define NTILES    (2 * NTILES_P1)  // 4096
#define GRID      456              // 152 SMs x 3 resident CTAs

// Intermediate (W-filtered) image in fp16, same NHWC index space as x.
__device__ __half g_scratch[(size_t)NN * HH * WW * CC];
__device__ int    g_queue;         // next queue slot
__device__ int    g_done[NN];      // pass1 rows completed per image

__global__ void init_kernel() {
    if (threadIdx.x == 0) g_queue = 0;
    if (threadIdx.x < NN) g_done[threadIdx.x] = 0;
}

// ---- R7 tile bodies, verbatim ----

// Fwd+bwd IIR (a=b=0.5) over a ROWLEN x CC half2 tile in smem, in place.
// fp32 carry chains in registers; boundary chunks exact w.r.t. reference
// inits (carry = s[0] fwd; carry = s[L-1] = y_f[L-1] bwd).
__device__ __forceinline__ void iir_scan_tile_h2(__half2* s, int tid) {
    const int c     = tid & 31;
    const int chunk = tid >> 5;
    const int w0    = chunk * CLEN;
    const int w1    = w0 + CLEN;

    int ws = w0 - LWARM; if (ws < 0) ws = 0;
    float2 carry = __half22float2(s[ws * H2PW + c]);
    for (int w = ws; w < w0; ++w) {
        const float2 v = __half22float2(s[w * H2PW + c]);
        carry.x = fmaf(0.5f, carry.x, 0.5f * v.x);
        carry.y = fmaf(0.5f, carry.y, 0.5f * v.y);
    }
    __syncthreads();

    #pragma unroll
    for (int w = w0; w < w1; ++w) {
        const float2 v = __half22float2(s[w * H2PW + c]);
        carry.x = fmaf(0.5f, carry.x, 0.5f * v.x);
        carry.y = fmaf(0.5f, carry.y, 0.5f * v.y);
        s[w * H2PW + c] = __floats2half2_rn(carry.x, carry.y);
    }
    __syncthreads();

    int we = w1 - 1 + LWARM; if (we > ROWLEN - 1) we = ROWLEN - 1;
    carry = __half22float2(s[we * H2PW + c]);
    for (int w = we - 1; w >= w1; --w) {
        const float2 v = __half22float2(s[w * H2PW + c]);
        carry.x = fmaf(0.5f, carry.x, 0.5f * v.x);
        carry.y = fmaf(0.5f, carry.y, 0.5f * v.y);
    }
    __syncthreads();

    #pragma unroll
    for (int w = w1 - 1; w >= w0; --w) {
        const float2 v = __half22float2(s[w * H2PW + c]);
        carry.x = fmaf(0.5f, carry.x, 0.5f * v.x);
        carry.y = fmaf(0.5f, carry.y, 0.5f * v.y);
        s[w * H2PW + c] = __floats2half2_rn(carry.x, carry.y);
    }
    __syncthreads();
}

// W-direction IIR over row `nh` (= n*HH + h): x fp32 -> scan -> scratch fp16.
__device__ __forceinline__ void do_pass1(const float* __restrict__ x,
                                         int nh, __half2* s2) {
    uint4* s4 = reinterpret_cast<uint4*>(s2);
    const size_t base = (size_t)nh * (WW * CC);

    #pragma unroll
    for (int i = threadIdx.x; i < VECH; i += THREADS) {
        const int w = i >> 3;
        const int q = i & 7;
        const float4 a = *(const float4*)(x + base + (size_t)w * CC + q * 8);
        const float4 b = *(const float4*)(x + base + (size_t)w * CC + q * 8 + 4);
        __half2 hv[4];
        hv[0] = __floats2half2_rn(a.x, a.y);
        hv[1] = __floats2half2_rn(a.z, a.w);
        hv[2] = __floats2half2_rn(b.x, b.y);
        hv[3] = __floats2half2_rn(b.z, b.w);
        s4[w * 8 + q] = *(uint4*)hv;
    }
    __syncthreads();

    iir_scan_tile_h2(s2, threadIdx.x);

    #pragma unroll
    for (int i = threadIdx.x; i < VECH; i += THREADS) {
        const int w = i >> 3;
        const int q = i & 7;
        *(uint4*)(g_scratch + base + (size_t)w * CC + q * 8) = s4[w * 8 + q];
    }
}

// H-direction IIR over column `nw` (= n*WW + w) + residual mix -> out.
__device__ __forceinline__ void do_pass2(const float* __restrict__ x,
                                         const float* sm,   // sigmoid(alpha)
                                         float* __restrict__ out,
                                         int nw, __half2* s2) {
    uint4* s4 = reinterpret_cast<uint4*>(s2);
    const int    n    = nw >> 9;
    const int    w    = nw & 511;
    const size_t base = (size_t)n * (HH * WW * CC) + (size_t)w * CC;

    #pragma unroll
    for (int i = threadIdx.x; i < VECH; i += THREADS) {
        const int h = i >> 3;
        const int q = i & 7;
        s4[h * 8 + q] = *(const uint4*)(g_scratch + base + (size_t)h * (WW * CC) + q * 8);
    }
    __syncthreads();

    iir_scan_tile_h2(s2, threadIdx.x);

    #pragma unroll
    for (int i = threadIdx.x; i < VEC; i += THREADS) {
        const int    h  = i >> 4;                   // 16 float4 per h
        const int    c4 = i & 15;
        const size_t g  = base + (size_t)h * (WW * CC) + c4 * 4;
        const float4 xv = *(const float4*)(x + g);
        const __half2* hp = (const __half2*)(s2 + h * H2PW + c4 * 2);
        const float2 y0 = __half22float2(hp[0]);
        const float2 y1 = __half22float2(hp[1]);
        const float4 mv = *(const float4*)(&sm[c4 * 4]);
        float4 o;
        o.x = fmaf(mv.x, y0.x - xv.x, xv.x);
        o.y = fmaf(mv.y, y0.y - xv.y, xv.y);
        o.z = fmaf(mv.z, y1.x - xv.z, xv.z);
        o.w = fmaf(mv.w, y1.y - xv.w, xv.w);
        *(float4*)(out + g) = o;
    }
}

// Two-segment queue: [all 2048 p1 tiles][all 2048 p2 tiles, image order].
// By the time any p2(image n) tile is claimed, p1(image n) finished waves
// earlier (p2 segment starts only after every p1 tile is CLAIMED, and image
// order means image-n consumers come ~n*512 slots later). The g_done spin is
// a correctness guard that almost never triggers.
__global__ void __launch_bounds__(THREADS, 3)
iir_persistent_kernel(const float* __restrict__ x,
                      const float* __restrict__ alpha,
                      float*       __restrict__ out) {
    extern __shared__ __half2 s2[];
    __shared__ __align__(16) float sm[CPB];
    __shared__ int s_q;

    if (threadIdx.x < CPB)
        sm[threadIdx.x] = 1.0f / (1.0f + expf(-alpha[threadIdx.x]));
    // sm is read only in p2 epilogues, always separated from here by syncs.

    while (true) {
        if (threadIdx.x == 0) s_q = atomicAdd(&g_queue, 1);
        __syncthreads();                    // claim visible + smem reuse fence
        const int q = s_q;
        if (q >= NTILES) break;

        if (q < NTILES_P1) {
            do_pass1(x, q, s2);
            __threadfence();                // publish scratch stores (all threads)
            __syncthreads();
            if (threadIdx.x == 0)
                atomicAdd(&g_done[q >> 9], 1);
        } else {
            const int tile = q - NTILES_P1;
            if (threadIdx.x == 0) {
                const int n = tile >> 9;
                while (atomicAdd(&g_done[n], 0) < HH) __nanosleep(64);
                __threadfence();            // acquire scratch visibility
            }
            __syncthreads();
            do_pass2(x, sm, out, tile, s2);
        }
    }
}

extern "C" void kernel_launch(void* const* d_in, const int* in_sizes, int n_in,
                              void* d_out, int out_size) {
    const float* x     = (const float*)d_in[0];
    const float* alpha = (const float*)d_in[1];
    float*       out   = (float*)d_out;

    // >48KB dynamic smem opt-in (idempotent, capture-safe).
    cudaFuncSetAttribute(iir_persistent_kernel,
                         cudaFuncAttributeMaxDynamicSharedMemorySize, SMEM_BYTES);

    init_kernel<<<1, 32>>>();
    iir_persistent_kernel<<<GRID, THREADS, SMEM_BYTES>>>(x, alpha, out);
}

// round 12
// speedup vs baseline: 1.4304x; 1.2912x over previous
#include <cuda_runtime.h>
#include <cuda_fp16.h>
#include <math.h>

// Problem dims (fixed by the dataset)
#define NN 4
#define HH 512
#define WW 512
#define CC 64

#define CPB     64                 // channels per tile = full row
#define THREADS 512
#define ROWLEN  512
#define NCHUNK  16                 // one warp per chunk; lane = half2 channel pair
#define CLEN    (ROWLEN / NCHUNK)  // 32
#define LWARM   16                 // warm-up: err ~ 0.5^17 ~ 8e-6
#define H2PW    (CPB / 2)          // half2 per scan-site = 32
#define VECH    (ROWLEN * CPB / 8) // uint4 (8 halves) per fp16 tile = 4096
#define SMEM_BYTES (ROWLEN * CPB * 2) // 65536 (fp16 tile -> 3 CTAs/SM)

#define ZCOL    (HH * CC)          // elements per z column blob = 32768

// W-filtered image, fp16, W-MAJOR layout: z[n][w][h][c].
// pass1 (row tiles) writes it with full-line stores; pass2 (column tiles)
// reads one contiguous 64KB blob per tile, and its w+-1 neighbors (L2-hot)
// to reconstruct x via the exact filter inverse.
__device__ __half g_scratch[(size_t)NN * HH * WW * CC];

// ---- R7 scan body, verbatim ----
// Fwd+bwd IIR (a=b=0.5) over a ROWLEN x CC half2 tile in smem, in place.
// fp32 carry chains in registers; boundary chunks exact w.r.t. reference
// inits (carry = s[0] fwd; carry = s[L-1] = y_f[L-1] bwd).
__device__ __forceinline__ void iir_scan_tile_h2(__half2* s, int tid) {
    const int c     = tid & 31;
    const int chunk = tid >> 5;
    const int w0    = chunk * CLEN;
    const int w1    = w0 + CLEN;

    int ws = w0 - LWARM; if (ws < 0) ws = 0;
    float2 carry = __half22float2(s[ws * H2PW + c]);
    for (int w = ws; w < w0; ++w) {
        const float2 v = __half22float2(s[w * H2PW + c]);
        carry.x = fmaf(0.5f, carry.x, 0.5f * v.x);
        carry.y = fmaf(0.5f, carry.y, 0.5f * v.y);
    }
    __syncthreads();

    #pragma unroll
    for (int w = w0; w < w1; ++w) {
        const float2 v = __half22float2(s[w * H2PW + c]);
        carry.x = fmaf(0.5f, carry.x, 0.5f * v.x);
        carry.y = fmaf(0.5f, carry.y, 0.5f * v.y);
        s[w * H2PW + c] = __floats2half2_rn(carry.x, carry.y);
    }
    __syncthreads();

    int we = w1 - 1 + LWARM; if (we > ROWLEN - 1) we = ROWLEN - 1;
    carry = __half22float2(s[we * H2PW + c]);
    for (int w = we - 1; w >= w1; --w) {
        const float2 v = __half22float2(s[w * H2PW + c]);
        carry.x = fmaf(0.5f, carry.x, 0.5f * v.x);
        carry.y = fmaf(0.5f, carry.y, 0.5f * v.y);
    }
    __syncthreads();

    #pragma unroll
    for (int w = w1 - 1; w >= w0; --w) {
        const float2 v = __half22float2(s[w * H2PW + c]);
        carry.x = fmaf(0.5f, carry.x, 0.5f * v.x);
        carry.y = fmaf(0.5f, carry.y, 0.5f * v.y);
        s[w * H2PW + c] = __floats2half2_rn(carry.x, carry.y);
    }
    __syncthreads();
}

// Pass 1: IIR along W over row (n,h). Reads x (NHWC fp32), writes z in
// w-major fp16 layout. Store: per w, 64 ch = 128B line at 64KB stride.
__global__ void __launch_bounds__(THREADS, 3)
pass1_kernel(const float* __restrict__ x) {
    extern __shared__ __half2 s2[];
    uint4* s4 = reinterpret_cast<uint4*>(s2);

    const int    nh    = blockIdx.x;                // n*HH + h
    const int    n     = nh >> 9;
    const int    h     = nh & 511;
    const size_t xbase = (size_t)nh * (WW * CC);
    const size_t zbase = ((size_t)n * WW) * ZCOL + (size_t)h * CC;

    #pragma unroll
    for (int i = threadIdx.x; i < VECH; i += THREADS) {
        const int w = i >> 3;
        const int q = i & 7;
        const float4 a = *(const float4*)(x + xbase + (size_t)w * CC + q * 8);
        const float4 b = *(const float4*)(x + xbase + (size_t)w * CC + q * 8 + 4);
        __half2 hv[4];
        hv[0] = __floats2half2_rn(a.x, a.y);
        hv[1] = __floats2half2_rn(a.z, a.w);
        hv[2] = __floats2half2_rn(b.x, b.y);
        hv[3] = __floats2half2_rn(b.z, b.w);
        s4[w * 8 + q] = *(uint4*)hv;
    }
    __syncthreads();

    iir_scan_tile_h2(s2, threadIdx.x);

    // z[n][w][h][c]: per w a full 128B line (8 uint4), stride 64KB in w.
    #pragma unroll
    for (int i = threadIdx.x; i < VECH; i += THREADS) {
        const int w = i >> 3;
        const int q = i & 7;
        *(uint4*)(g_scratch + zbase + (size_t)w * ZCOL + q * 8) = s4[w * 8 + q];
    }
}

// Pass 2: IIR along H over column (n,w). Loads one contiguous z blob,
// scans, then reconstructs x from z[w-1], z[w], z[w+1] (exact filter
// inverse) and writes the residual mix. Never touches x's fp32 array.
__global__ void __launch_bounds__(THREADS, 3)
pass2_kernel(const float* __restrict__ alpha,
             float*       __restrict__ out) {
    extern __shared__ __half2 s2[];
    uint4* s4 = reinterpret_cast<uint4*>(s2);
    __shared__ __align__(16) float sm[CPB];

    const int    nw    = blockIdx.x;                // n*WW + w
    const int    n     = nw >> 9;
    const int    w     = nw & 511;
    const size_t zbase = ((size_t)n * WW + w) * ZCOL;
    const size_t obase = (size_t)n * (HH * WW * CC) + (size_t)w * CC;

    if (threadIdx.x < CPB)
        sm[threadIdx.x] = 1.0f / (1.0f + expf(-alpha[threadIdx.x]));

    // z column blob: contiguous 64KB copy into smem ([h][c] tile).
    const uint4* zc = (const uint4*)(g_scratch + zbase);
    #pragma unroll
    for (int i = threadIdx.x; i < VECH; i += THREADS)
        s4[i] = zc[i];
    __syncthreads();

    iir_scan_tile_h2(s2, threadIdx.x);

    // Exact inverse of the W filter (derived from the reference recurrences):
    //   w in [1,510]: x = 5 z[w] - 2 z[w-1] - 2 z[w+1]
    //   w = 0:        x = 2 z[0] - z[1]
    //   w = 511:      x = 3 z[511] - 2 z[510]
    float cm, c0, cp;
    const __half *zm, *zp;
    if (w == 0)        { cm = 0.f;  c0 = 2.f; cp = -1.f;
                         zm = g_scratch + zbase; zp = g_scratch + zbase + ZCOL; }
    else if (w == 511) { cm = -2.f; c0 = 3.f; cp = 0.f;
                         zm = g_scratch + zbase - ZCOL; zp = g_scratch + zbase; }
    else               { cm = -2.f; c0 = 5.f; cp = -2.f;
                         zm = g_scratch + zbase - ZCOL; zp = g_scratch + zbase + ZCOL; }
    const __half* z0 = g_scratch + zbase;   // re-read own column (L2-hot)

    // Epilogue: per i -> (h, q) = 8 channels; reads 3x 16B z (gmem, L2-hot)
    // + 16B y (smem); writes 32B out. Independent iterations, full MLP.
    #pragma unroll
    for (int i = threadIdx.x; i < VECH; i += THREADS) {
        const int    h  = i >> 3;
        const int    q  = i & 7;
        const size_t zo = (size_t)h * CC + q * 8;
        const uint4  u0 = *(const uint4*)(z0 + zo);
        const uint4  um = *(const uint4*)(zm + zo);
        const uint4  up = *(const uint4*)(zp + zo);
        const __half2* h0 = (const __half2*)&u0;
        const __half2* hm = (const __half2*)&um;
        const __half2* hp = (const __half2*)&up;
        const __half2* hy = s2 + h * H2PW + q * 4;

        float outv[8];
        #pragma unroll
        for (int k = 0; k < 4; ++k) {
            const float2 v0 = __half22float2(h0[k]);
            const float2 vm = __half22float2(hm[k]);
            const float2 vp = __half22float2(hp[k]);
            const float2 yv = __half22float2(hy[k]);
            const float2 mv = *(const float2*)(&sm[q * 8 + k * 2]);
            float xr, xi;
            xr = fmaf(c0, v0.x, fmaf(cm, vm.x, cp * vp.x));
            xi = fmaf(c0, v0.y, fmaf(cm, vm.y, cp * vp.y));
            outv[2 * k]     = fmaf(mv.x, yv.x - xr, xr);
            outv[2 * k + 1] = fmaf(mv.y, yv.y - xi, xi);
        }
        float* op = out + obase + (size_t)h * (WW * CC) + q * 8;
        *(float4*)op       = *(float4*)&outv[0];
        *(float4*)(op + 4) = *(float4*)&outv[4];
    }
}

extern "C" void kernel_launch(void* const* d_in, const int* in_sizes, int n_in,
                              void* d_out, int out_size) {
    const float* x     = (const float*)d_in[0];
    const float* alpha = (const float*)d_in[1];
    float*       out   = (float*)d_out;

    // >48KB dynamic smem opt-in (idempotent, capture-safe).
    cudaFuncSetAttribute(pass1_kernel,
                         cudaFuncAttributeMaxDynamicSharedMemorySize, SMEM_BYTES);
    cudaFuncSetAttribute(pass2_kernel,
                         cudaFuncAttributeMaxDynamicSharedMemorySize, SMEM_BYTES);

    pass1_kernel<<<NN * HH, THREADS, SMEM_BYTES>>>(x);
    pass2_kernel<<<NN * WW, THREADS, SMEM_BYTES>>>(alpha, out);
}